// round 17
// baseline (speedup 1.0000x reference)
#include <cuda_runtime.h>
#include <cuda_fp16.h>
#include <math.h>
#include <stdint.h>

#define TOK   2048
#define HD    1024
#define ID    1024
#define NE    32
#define TOPK  4
#define TWOI  2048
#define PAIRS (TOK*TOPK)
#define LIMITF 7.0f
#define ALPHAF 1.702f

// -------- device scratch --------
__device__ int    g_count[NE];
__device__ int    g_offset[NE];
__device__ int    g_cursor[NE];
__device__ int    g_topk_idx[TOK * TOPK];
__device__ float  g_topk_w[TOK * TOPK];
__device__ int    g_pair_of[TOK * TOPK];
__device__ __half g_xh[(size_t)PAIRS * HD];    // gathered fp16 token rows (16MB)
__device__ __half g_acth[(size_t)PAIRS * ID];  // fp16 activated intermediate (16MB)
__device__ float  g_y[(size_t)PAIRS * HD];     // down GEMM output (32MB)

// -------- helpers --------
__device__ __forceinline__ void mma_f16(float* d, const uint32_t* a, const uint32_t* b) {
    asm volatile(
        "mma.sync.aligned.m16n8k16.row.col.f32.f16.f16.f32 "
        "{%0,%1,%2,%3}, {%4,%5,%6,%7}, {%8,%9}, {%0,%1,%2,%3};\n"
        : "+f"(d[0]), "+f"(d[1]), "+f"(d[2]), "+f"(d[3])
        : "r"(a[0]), "r"(a[1]), "r"(a[2]), "r"(a[3]),
          "r"(b[0]), "r"(b[1]));
}
__device__ __forceinline__ uint32_t h2u(__half2 h) { return *(uint32_t*)&h; }
__device__ __forceinline__ void cp16(void* s, const void* g) {
    unsigned sa = (unsigned)__cvta_generic_to_shared(s);
    asm volatile("cp.async.cg.shared.global [%0], [%1], 16;\n" :: "r"(sa), "l"(g));
}
#define CP_COMMIT() asm volatile("cp.async.commit_group;\n" ::: "memory")
#define CP_WAIT2()  asm volatile("cp.async.wait_group 2;\n" ::: "memory")

// -------- grouped fp16 GEMM, 256 thr, 128x128 tile, BK=16 --------
// A: fp16 smem [2][128][16] halves, PERMUTED word order [w0,w4,w1,w5,w2,w6,w3,w7]
//    per 16-half k-chunk -> every fragment pair is one conflict-free LDS.64.
// B: fp32 smem [4][16][132] via 4-stage cp.async ring; pack to fp16 at frag load.
// FIRST:  A = g_xh rows,   W = gate_up (ldb=2048), out = g_acth (fused act, fp16)
// !FIRST: A = g_acth rows, W = down    (ldb=1024), out = g_y (fp32)
template<bool FIRST>
__global__ __launch_bounds__(256, 2) void moe_gemm(const float* __restrict__ W,
                                                   const float* __restrict__ gub) {
    const int LDBW = FIRST ? TWOI : HD;
    const int bx = blockIdx.x;
    const int e  = blockIdx.y >> 4;
    const int rt = blockIdx.y & 15;
    const int base = g_offset[e];
    const int cnt  = g_count[e];
    const int row0 = rt * 128;
    if (row0 >= cnt) return;

    __shared__ __align__(16) __half As[2][128][16];
    __shared__ __align__(16) float  Bsf[4][16][132];

    const int tid  = threadIdx.x;
    const int lane = tid & 31;
    const int wid  = tid >> 5;
    const int wm   = wid >> 2;         // 0..1
    const int wn   = wid & 3;          // 0..3
    const int lr   = lane >> 2;        // 0..7
    const int lc   = lane & 3;         // 0..3

    // A staging: thread -> (row tid>>1, perm group g=tid&1).
    // Loads words {g*2, g*2+1} (halves g*4..) and {g*2+4, g*2+5} (halves g*4+8..),
    // stores permuted uint4 {u0.x,u1.x,u0.y,u1.y} at half offset g*8.
    const int rowA = tid >> 1;
    const int gA   = tid & 1;
    int ar = row0 + rowA; if (ar >= cnt) ar = cnt - 1;
    const __half* aSrc = (FIRST ? (const __half*)g_xh : (const __half*)g_acth)
                         + (size_t)(base + ar) * 1024 + gA * 4;

    // B staging via cp.async: thread -> (k row tid>>4, col chunk (tid&15)*8), 2x 16B
    const int rB = tid >> 4;           // 0..15
    const int cB = (tid & 15) * 8;     // 0..120
    const float* bSrc = W + ((size_t)e * 1024 + rB) * LDBW + bx * 128 + cB;

    float acc[4][4][4];
    #pragma unroll
    for (int i = 0; i < 4; i++)
        #pragma unroll
        for (int j = 0; j < 4; j++)
            #pragma unroll
            for (int q = 0; q < 4; q++) acc[i][j][q] = 0.f;

    const int NK = 64;   // 1024/16

    // ---- prologue: issue B stages 0..2; stage A tile 0 ----
    #pragma unroll
    for (int s = 0; s < 3; s++) {
        const float* src = bSrc + (size_t)s * 16 * LDBW;
        cp16(&Bsf[s][rB][cB],     src);
        cp16(&Bsf[s][rB][cB + 4], src + 4);
        CP_COMMIT();
    }
    {
        uint2 u0 = *(const uint2*)aSrc;
        uint2 u1 = *(const uint2*)(aSrc + 8);
        *(uint4*)&As[0][rowA][gA * 8] = make_uint4(u0.x, u1.x, u0.y, u1.y);
    }

    #pragma unroll 1
    for (int kt = 0; kt < NK; kt++) {
        // A register prefetch for kt+1 (LDG overlapped with wait + compute)
        uint2 p0, p1;
        if (kt + 1 < NK) {
            p0 = *(const uint2*)(aSrc + (kt + 1) * 16);
            p1 = *(const uint2*)(aSrc + (kt + 1) * 16 + 8);
        }

        CP_WAIT2();            // B stage kt complete (3 groups in flight)
        __syncthreads();

        const int ab = kt & 1;
        const int bs = kt & 3;

        // B fragments: fp32 loads + pack (conflict-free banks)
        uint32_t bf[4][2];
        #pragma unroll
        for (int nt = 0; nt < 4; nt++) {
            const int n = wn * 32 + nt * 8 + lr;
            float b00 = Bsf[bs][2 * lc][n];
            float b01 = Bsf[bs][2 * lc + 1][n];
            float b10 = Bsf[bs][2 * lc + 8][n];
            float b11 = Bsf[bs][2 * lc + 9][n];
            bf[nt][0] = h2u(__floats2half2_rn(b00, b01));
            bf[nt][1] = h2u(__floats2half2_rn(b10, b11));
        }
        #pragma unroll
        for (int mt = 0; mt < 4; mt++) {
            const int r = wm * 64 + mt * 16 + lr;
            // permuted layout: one LDS.64 gives (a0,a2); row+8 gives (a1,a3)
            uint2 lo = *(const uint2*)&As[ab][r][4 * lc];
            uint2 hi = *(const uint2*)&As[ab][r + 8][4 * lc];
            uint32_t af[4] = { lo.x, hi.x, lo.y, hi.y };
            #pragma unroll
            for (int nt = 0; nt < 4; nt++)
                mma_f16(acc[mt][nt], af, bf[nt]);
        }

        // stage A(kt+1) into the alternate buffer (not read this iteration)
        if (kt + 1 < NK)
            *(uint4*)&As[(kt + 1) & 1][rowA][gA * 8] = make_uint4(p0.x, p1.x, p0.y, p1.y);

        // issue B stage kt+3 (buffer last consumed at kt-1; safe post-sync)
        if (kt + 3 < NK) {
            const float* src = bSrc + (size_t)(kt + 3) * 16 * LDBW;
            cp16(&Bsf[(kt + 3) & 3][rB][cB],     src);
            cp16(&Bsf[(kt + 3) & 3][rB][cB + 4], src + 4);
        }
        CP_COMMIT();
    }

    // ---- epilogue ----
    if (FIRST) {
        const float* gb = gub + (size_t)e * TWOI;
        #pragma unroll
        for (int mt = 0; mt < 4; mt++) {
            #pragma unroll
            for (int half = 0; half < 2; half++) {
                const int grow = row0 + wm * 64 + mt * 16 + lr + half * 8;
                if (grow < cnt) {
                    __half* orow = g_acth + (size_t)(base + grow) * ID;
                    #pragma unroll
                    for (int nt = 0; nt < 4; nt++) {
                        const int i = bx * 64 + wn * 16 + nt * 4 + lc;
                        float gate = acc[mt][nt][half * 2 + 0] + gb[2 * i];
                        float up   = acc[mt][nt][half * 2 + 1] + gb[2 * i + 1];
                        gate = fminf(gate, LIMITF);
                        up   = fminf(fmaxf(up, -LIMITF), LIMITF);
                        float glu = gate / (1.f + __expf(-gate * ALPHAF));
                        orow[i] = __float2half((up + 1.f) * glu);
                    }
                }
            }
        }
    } else {
        #pragma unroll
        for (int mt = 0; mt < 4; mt++) {
            #pragma unroll
            for (int half = 0; half < 2; half++) {
                const int grow = row0 + wm * 64 + mt * 16 + lr + half * 8;
                if (grow < cnt) {
                    float* orow = g_y + (size_t)(base + grow) * HD;
                    #pragma unroll
                    for (int nt = 0; nt < 4; nt++) {
                        const int c = bx * 128 + wn * 32 + nt * 8 + 2 * lc;
                        *(float2*)(orow + c) = make_float2(acc[mt][nt][half * 2 + 0],
                                                           acc[mt][nt][half * 2 + 1]);
                    }
                }
            }
        }
    }
}

// -------- K0: reset counters --------
__global__ void reset_kernel() {
    int i = threadIdx.x;
    if (i < NE) g_count[i] = 0;
}

// -------- K1: router (4 tokens per block) --------
__global__ __launch_bounds__(256) void router_kernel(const float* __restrict__ x,
                                                     const float* __restrict__ rw,
                                                     const float* __restrict__ rb,
                                                     float* __restrict__ scores_out) {
    const int t0   = blockIdx.x * 4;
    const int tid  = threadIdx.x;
    const int warp = tid >> 5;
    const int lane = tid & 31;

    __shared__ float xs[4][HD];
    __shared__ float logits[4][NE];

    #pragma unroll
    for (int j = 0; j < 4; j++) {
        const int f   = tid * 4 + j;
        const int row = f >> 8;
        const int col = (f & 255) * 4;
        *(float4*)&xs[row][col] = *(const float4*)(x + (size_t)(t0 + row) * HD + col);
    }
    __syncthreads();

    for (int e = warp; e < NE; e += 8) {
        const float* w = rw + (size_t)e * HD;
        float s0 = 0.f, s1 = 0.f, s2 = 0.f, s3 = 0.f;
        for (int h = lane; h < HD; h += 32) {
            float wv = w[h];
            s0 += xs[0][h] * wv;
            s1 += xs[1][h] * wv;
            s2 += xs[2][h] * wv;
            s3 += xs[3][h] * wv;
        }
        #pragma unroll
        for (int off = 16; off; off >>= 1) {
            s0 += __shfl_down_sync(0xffffffffu, s0, off);
            s1 += __shfl_down_sync(0xffffffffu, s1, off);
            s2 += __shfl_down_sync(0xffffffffu, s2, off);
            s3 += __shfl_down_sync(0xffffffffu, s3, off);
        }
        if (lane == 0) {
            float b = rb[e];
            logits[0][e] = s0 + b;
            logits[1][e] = s1 + b;
            logits[2][e] = s2 + b;
            logits[3][e] = s3 + b;
        }
    }
    __syncthreads();

    if (warp < 4) {
        const int t = t0 + warp;
        float cur = logits[warp][lane];
        float sel_val[TOPK];
        int   sel_idx[TOPK];
        #pragma unroll
        for (int k = 0; k < TOPK; k++) {
            float bv = cur; int bi = lane;
            #pragma unroll
            for (int off = 16; off; off >>= 1) {
                float ov = __shfl_xor_sync(0xffffffffu, bv, off);
                int   oi = __shfl_xor_sync(0xffffffffu, bi, off);
                if (ov > bv || (ov == bv && oi < bi)) { bv = ov; bi = oi; }
            }
            sel_val[k] = bv; sel_idx[k] = bi;
            if (lane == bi) cur = -1e30f;
        }
        float m = sel_val[0];
        float ex[TOPK]; float sum = 0.f;
        #pragma unroll
        for (int k = 0; k < TOPK; k++) { ex[k] = expf(sel_val[k] - m); sum += ex[k]; }
        float inv = 1.f / sum;

        float sc = 0.f;
        #pragma unroll
        for (int k = 0; k < TOPK; k++) if (lane == sel_idx[k]) sc = ex[k] * inv;
        scores_out[(size_t)t * NE + lane] = sc;

        if (lane < TOPK) {
            g_topk_idx[t * TOPK + lane] = sel_idx[lane];
            g_topk_w[t * TOPK + lane]   = ex[lane] * inv;
            atomicAdd(&g_count[sel_idx[lane]], 1);
        }
    }
}

// -------- K2: prefix sum --------
__global__ void prefix_kernel() {
    if (threadIdx.x == 0) {
        int acc = 0;
        for (int e = 0; e < NE; e++) {
            g_offset[e] = acc;
            g_cursor[e] = acc;
            acc += g_count[e];
        }
    }
}

// -------- K3: fused scatter + gather/convert (one block per token) --------
__global__ __launch_bounds__(128) void scatgather_kernel(const float* __restrict__ x) {
    const int t   = blockIdx.x;
    const int tid = threadIdx.x;
    __shared__ int spos[TOPK];

    if (tid < TOPK) {
        int e   = g_topk_idx[t * TOPK + tid];
        int pos = atomicAdd(&g_cursor[e], 1);
        spos[tid] = pos;
        g_pair_of[t * TOPK + tid] = pos;
    }
    __syncthreads();

    const float* src = x + (size_t)t * HD + tid * 8;
    float4 v0 = *(const float4*)src;
    float4 v1 = *(const float4*)(src + 4);
    uint4 u;
    u.x = h2u(__floats2half2_rn(v0.x, v0.y));
    u.y = h2u(__floats2half2_rn(v0.z, v0.w));
    u.z = h2u(__floats2half2_rn(v1.x, v1.y));
    u.w = h2u(__floats2half2_rn(v1.z, v1.w));
    #pragma unroll
    for (int k = 0; k < TOPK; k++)
        *(uint4*)(g_xh + (size_t)spos[k] * HD + tid * 8) = u;
}

// -------- K7: weighted combine + down bias --------
__global__ void combine_kernel(const float* __restrict__ db,
                               float* __restrict__ out) {
    size_t idx = (size_t)blockIdx.x * blockDim.x + threadIdx.x;
    if (idx >= (size_t)TOK * HD) return;
    int t = (int)(idx >> 10);
    int h = (int)(idx & 1023);
    float s = 0.f;
    #pragma unroll
    for (int k = 0; k < TOPK; k++) {
        int   p = g_pair_of[t * TOPK + k];
        int   e = g_topk_idx[t * TOPK + k];
        float w = g_topk_w[t * TOPK + k];
        s += w * (g_y[(size_t)p * HD + h] + db[(size_t)e * HD + h]);
    }
    out[(size_t)t * HD + h] = s;
}

// -------- launch --------
extern "C" void kernel_launch(void* const* d_in, const int* in_sizes, int n_in,
                              void* d_out, int out_size) {
    const float* hidden  = (const float*)d_in[0];
    const float* gate_up = (const float*)d_in[1];
    const float* gub     = (const float*)d_in[2];
    const float* down    = (const float*)d_in[3];
    const float* db      = (const float*)d_in[4];
    const float* rw      = (const float*)d_in[5];
    const float* rb      = (const float*)d_in[6];

    float* out_routed = (float*)d_out;
    float* out_scores = (float*)d_out + (size_t)TOK * HD;

    reset_kernel<<<1, 32>>>();
    router_kernel<<<TOK / 4, 256>>>(hidden, rw, rb, out_scores);
    prefix_kernel<<<1, 32>>>();
    scatgather_kernel<<<TOK, 128>>>(hidden);

    moe_gemm<true><<<dim3(16, NE * 16), 256>>>(gate_up, gub);
    moe_gemm<false><<<dim3(8, NE * 16), 256>>>(down, nullptr);
    combine_kernel<<<((size_t)TOK * HD + 255) / 256, 256>>>(db, out_routed);
}